// round 14
// baseline (speedup 1.0000x reference)
#include <cuda_runtime.h>
#include <cstdint>

// compressor_17454747091102: 8-voter bitwise majority vote.
// out packed word j, bit i = 1 iff >=5 of 8 voters have bit i of word j set.
// Output dtype float32: store (float)(int32)packed_word.
//
// Warm-path (L2-resident across graph replays) via ld.global.nc + evict_last:
// timed 8.13 -> 7.17 (R12) -> 7.10 (R13, +hints). This round: identical memory
// ops, occupancy 55% -> ~85-100% via __launch_bounds__(256,8) to test whether
// the warm floor is L2-consumption-parallelism-bound.

__device__ __forceinline__ void fa(uint32_t a, uint32_t b, uint32_t c,
                                   uint32_t& s, uint32_t& cy) {
    s  = a ^ b ^ c;
    cy = (a & b) | (c & (a ^ b));   // one LOP3 each
}

__device__ __forceinline__ uint32_t maj8(uint32_t w0, uint32_t w1, uint32_t w2,
                                         uint32_t w3, uint32_t w4, uint32_t w5,
                                         uint32_t w6, uint32_t w7) {
    uint32_t sa, ca, sb, cb;
    fa(w0, w1, w2, sa, ca);
    fa(w3, w4, w5, sb, cb);
    uint32_t sc = w6 ^ w7;
    uint32_t cc = w6 & w7;
    uint32_t S0, cd;
    fa(sa, sb, sc, S0, cd);
    uint32_t s1p, ce;
    fa(ca, cb, cc, s1p, ce);
    uint32_t S1 = s1p ^ cd;
    uint32_t cf = s1p & cd;
    uint32_t S2 = ce ^ cf;
    uint32_t S3 = ce & cf;
    // popcount = S0 + 2*S1 + 4*S2 + 8*S3 ; set iff >= 5
    return S3 | (S2 & (S1 | S0));
}

__device__ __forceinline__ uint64_t mk_policy_evict_last() {
    uint64_t p;
    asm("createpolicy.fractional.L2::evict_last.b64 %0, 1.0;" : "=l"(p));
    return p;
}

__device__ __forceinline__ uint64_t mk_policy_evict_first() {
    uint64_t p;
    asm("createpolicy.fractional.L2::evict_first.b64 %0, 1.0;" : "=l"(p));
    return p;
}

__device__ __forceinline__ uint4 ldg_nc_evl(const uint4* p, uint64_t pol) {
    uint4 v;
    asm volatile("ld.global.nc.L2::cache_hint.v4.u32 {%0,%1,%2,%3}, [%4], %5;"
                 : "=r"(v.x), "=r"(v.y), "=r"(v.z), "=r"(v.w)
                 : "l"(p), "l"(pol));
    return v;
}

__device__ __forceinline__ void st_evf(float4* p, float4 v, uint64_t pol) {
    asm volatile("st.global.L2::cache_hint.v4.f32 [%0], {%1,%2,%3,%4}, %5;"
                 :: "l"(p), "f"(v.x), "f"(v.y), "f"(v.z), "f"(v.w), "l"(pol)
                 : "memory");
}

__global__ void __launch_bounds__(256, 8)
majority_vote_kernel(const uint4* __restrict__ src, float4* __restrict__ out, int m4) {
    int idx = blockIdx.x * blockDim.x + threadIdx.x;
    if (idx >= m4) return;

    const uint64_t pol_in  = mk_policy_evict_last();
    const uint64_t pol_out = mk_policy_evict_first();

    // 8 independent 128-bit nc loads, evict_last.
    uint4 v0 = ldg_nc_evl(src + 0 * (size_t)m4 + idx, pol_in);
    uint4 v1 = ldg_nc_evl(src + 1 * (size_t)m4 + idx, pol_in);
    uint4 v2 = ldg_nc_evl(src + 2 * (size_t)m4 + idx, pol_in);
    uint4 v3 = ldg_nc_evl(src + 3 * (size_t)m4 + idx, pol_in);
    uint4 v4 = ldg_nc_evl(src + 4 * (size_t)m4 + idx, pol_in);
    uint4 v5 = ldg_nc_evl(src + 5 * (size_t)m4 + idx, pol_in);
    uint4 v6 = ldg_nc_evl(src + 6 * (size_t)m4 + idx, pol_in);
    uint4 v7 = ldg_nc_evl(src + 7 * (size_t)m4 + idx, pol_in);

    float4 r;
    r.x = __int2float_rn((int)maj8(v0.x, v1.x, v2.x, v3.x, v4.x, v5.x, v6.x, v7.x));
    r.y = __int2float_rn((int)maj8(v0.y, v1.y, v2.y, v3.y, v4.y, v5.y, v6.y, v7.y));
    r.z = __int2float_rn((int)maj8(v0.z, v1.z, v2.z, v3.z, v4.z, v5.z, v6.z, v7.z));
    r.w = __int2float_rn((int)maj8(v0.w, v1.w, v2.w, v3.w, v4.w, v5.w, v6.w, v7.w));
    st_evf(out + idx, r, pol_out);
}

extern "C" void kernel_launch(void* const* d_in, const int* in_sizes, int n_in,
                              void* d_out, int out_size) {
    const uint32_t* src = (const uint32_t*)d_in[1];
    long long n_src = in_sizes[1];
    if (n_in > 1 && in_sizes[0] > in_sizes[1]) { src = (const uint32_t*)d_in[0]; n_src = in_sizes[0]; }

    int M  = (int)(n_src / 8);     // packed words per voter == out_size
    int m4 = M / 4;                // uint4 chunks (262144)

    int threads = 256;
    int blocks  = (m4 + threads - 1) / threads;   // 1024
    majority_vote_kernel<<<blocks, threads>>>((const uint4*)src, (float4*)d_out, m4);
}

// round 15
// speedup vs baseline: 1.0075x; 1.0075x over previous
#include <cuda_runtime.h>
#include <cstdint>

// compressor_17454747091102: 8-voter bitwise majority vote.
// out packed word j, bit i = 1 iff >=5 of 8 voters have bit i of word j set.
// Output dtype float32: store (float)(int32)packed_word.
//
// Warm-path lineage: nc loads (R12, 8.13->7.17us) + evict_last/evict_first
// hints (R13, 7.10us). R14 showed capping regs (batch-split) costs 1.4us =>
// warm path rewards per-warp load batching over occupancy. This round deepens
// the batch: 16 front-batched nc uint4 loads per thread (2 chunks), ~72 regs.

__device__ __forceinline__ void fa(uint32_t a, uint32_t b, uint32_t c,
                                   uint32_t& s, uint32_t& cy) {
    s  = a ^ b ^ c;
    cy = (a & b) | (c & (a ^ b));   // one LOP3 each
}

__device__ __forceinline__ uint32_t maj8(uint32_t w0, uint32_t w1, uint32_t w2,
                                         uint32_t w3, uint32_t w4, uint32_t w5,
                                         uint32_t w6, uint32_t w7) {
    uint32_t sa, ca, sb, cb;
    fa(w0, w1, w2, sa, ca);
    fa(w3, w4, w5, sb, cb);
    uint32_t sc = w6 ^ w7;
    uint32_t cc = w6 & w7;
    uint32_t S0, cd;
    fa(sa, sb, sc, S0, cd);
    uint32_t s1p, ce;
    fa(ca, cb, cc, s1p, ce);
    uint32_t S1 = s1p ^ cd;
    uint32_t cf = s1p & cd;
    uint32_t S2 = ce ^ cf;
    uint32_t S3 = ce & cf;
    // popcount = S0 + 2*S1 + 4*S2 + 8*S3 ; set iff >= 5
    return S3 | (S2 & (S1 | S0));
}

__device__ __forceinline__ uint64_t mk_policy_evict_last() {
    uint64_t p;
    asm("createpolicy.fractional.L2::evict_last.b64 %0, 1.0;" : "=l"(p));
    return p;
}

__device__ __forceinline__ uint64_t mk_policy_evict_first() {
    uint64_t p;
    asm("createpolicy.fractional.L2::evict_first.b64 %0, 1.0;" : "=l"(p));
    return p;
}

__device__ __forceinline__ uint4 ldg_nc_evl(const uint4* p, uint64_t pol) {
    uint4 v;
    asm volatile("ld.global.nc.L2::cache_hint.v4.u32 {%0,%1,%2,%3}, [%4], %5;"
                 : "=r"(v.x), "=r"(v.y), "=r"(v.z), "=r"(v.w)
                 : "l"(p), "l"(pol));
    return v;
}

__device__ __forceinline__ void st_evf(float4* p, float4 v, uint64_t pol) {
    asm volatile("st.global.L2::cache_hint.v4.f32 [%0], {%1,%2,%3,%4}, %5;"
                 :: "l"(p), "f"(v.x), "f"(v.y), "f"(v.z), "f"(v.w), "l"(pol)
                 : "memory");
}

__global__ void __launch_bounds__(256)
majority_vote_kernel(const uint4* __restrict__ src, float4* __restrict__ out, int m4) {
    int t = blockIdx.x * blockDim.x + threadIdx.x;
    int i0 = t * 2;                 // adjacent pair of uint4 chunks
    if (i0 >= m4) return;
    int i1 = i0 + 1;

    const uint64_t pol_in  = mk_policy_evict_last();
    const uint64_t pol_out = mk_policy_evict_first();

    // 16 front-batched independent 128-bit nc loads (MLP = 16).
    uint4 a0 = ldg_nc_evl(src + 0 * (size_t)m4 + i0, pol_in);
    uint4 a1 = ldg_nc_evl(src + 1 * (size_t)m4 + i0, pol_in);
    uint4 a2 = ldg_nc_evl(src + 2 * (size_t)m4 + i0, pol_in);
    uint4 a3 = ldg_nc_evl(src + 3 * (size_t)m4 + i0, pol_in);
    uint4 a4 = ldg_nc_evl(src + 4 * (size_t)m4 + i0, pol_in);
    uint4 a5 = ldg_nc_evl(src + 5 * (size_t)m4 + i0, pol_in);
    uint4 a6 = ldg_nc_evl(src + 6 * (size_t)m4 + i0, pol_in);
    uint4 a7 = ldg_nc_evl(src + 7 * (size_t)m4 + i0, pol_in);
    uint4 b0 = ldg_nc_evl(src + 0 * (size_t)m4 + i1, pol_in);
    uint4 b1 = ldg_nc_evl(src + 1 * (size_t)m4 + i1, pol_in);
    uint4 b2 = ldg_nc_evl(src + 2 * (size_t)m4 + i1, pol_in);
    uint4 b3 = ldg_nc_evl(src + 3 * (size_t)m4 + i1, pol_in);
    uint4 b4 = ldg_nc_evl(src + 4 * (size_t)m4 + i1, pol_in);
    uint4 b5 = ldg_nc_evl(src + 5 * (size_t)m4 + i1, pol_in);
    uint4 b6 = ldg_nc_evl(src + 6 * (size_t)m4 + i1, pol_in);
    uint4 b7 = ldg_nc_evl(src + 7 * (size_t)m4 + i1, pol_in);

    float4 r;
    r.x = __int2float_rn((int)maj8(a0.x, a1.x, a2.x, a3.x, a4.x, a5.x, a6.x, a7.x));
    r.y = __int2float_rn((int)maj8(a0.y, a1.y, a2.y, a3.y, a4.y, a5.y, a6.y, a7.y));
    r.z = __int2float_rn((int)maj8(a0.z, a1.z, a2.z, a3.z, a4.z, a5.z, a6.z, a7.z));
    r.w = __int2float_rn((int)maj8(a0.w, a1.w, a2.w, a3.w, a4.w, a5.w, a6.w, a7.w));
    st_evf(out + i0, r, pol_out);

    r.x = __int2float_rn((int)maj8(b0.x, b1.x, b2.x, b3.x, b4.x, b5.x, b6.x, b7.x));
    r.y = __int2float_rn((int)maj8(b0.y, b1.y, b2.y, b3.y, b4.y, b5.y, b6.y, b7.y));
    r.z = __int2float_rn((int)maj8(b0.z, b1.z, b2.z, b3.z, b4.z, b5.z, b6.z, b7.z));
    r.w = __int2float_rn((int)maj8(b0.w, b1.w, b2.w, b3.w, b4.w, b5.w, b6.w, b7.w));
    st_evf(out + i1, r, pol_out);
}

extern "C" void kernel_launch(void* const* d_in, const int* in_sizes, int n_in,
                              void* d_out, int out_size) {
    const uint32_t* src = (const uint32_t*)d_in[1];
    long long n_src = in_sizes[1];
    if (n_in > 1 && in_sizes[0] > in_sizes[1]) { src = (const uint32_t*)d_in[0]; n_src = in_sizes[0]; }

    int M  = (int)(n_src / 8);     // packed words per voter == out_size
    int m4 = M / 4;                // uint4 chunks (262144)

    int threads = 256;
    int total_threads = m4 / 2;    // 2 chunks per thread
    int blocks = (total_threads + threads - 1) / threads;   // 512
    majority_vote_kernel<<<blocks, threads>>>((const uint4*)src, (float4*)d_out, m4);
}

// round 16
// speedup vs baseline: 1.1814x; 1.1726x over previous
#include <cuda_runtime.h>
#include <cstdint>

// compressor_17454747091102: 8-voter bitwise majority vote.
// out packed word j, bit i = 1 iff >=5 of 8 voters have bit i of word j set.
// Output dtype float32: store (float)(int32)packed_word.
//
// Warm-path optimum (R13, 7.10us): 8 front-batched uint4 nc+evict_last loads
// per thread, evict_first store, regs=38, no reg cap. R14/R15 showed both
// neighbors (more occ/less batch, more batch/less occ) regress ~1.4us.
// This round holds the per-thread schedule fixed and changes only geometry:
// block 256 -> 128 (grid 2048), packing ~1664 vs 1536 threads/SM at regs=38.

__device__ __forceinline__ void fa(uint32_t a, uint32_t b, uint32_t c,
                                   uint32_t& s, uint32_t& cy) {
    s  = a ^ b ^ c;
    cy = (a & b) | (c & (a ^ b));   // one LOP3 each
}

__device__ __forceinline__ uint32_t maj8(uint32_t w0, uint32_t w1, uint32_t w2,
                                         uint32_t w3, uint32_t w4, uint32_t w5,
                                         uint32_t w6, uint32_t w7) {
    uint32_t sa, ca, sb, cb;
    fa(w0, w1, w2, sa, ca);
    fa(w3, w4, w5, sb, cb);
    uint32_t sc = w6 ^ w7;
    uint32_t cc = w6 & w7;
    uint32_t S0, cd;
    fa(sa, sb, sc, S0, cd);
    uint32_t s1p, ce;
    fa(ca, cb, cc, s1p, ce);
    uint32_t S1 = s1p ^ cd;
    uint32_t cf = s1p & cd;
    uint32_t S2 = ce ^ cf;
    uint32_t S3 = ce & cf;
    // popcount = S0 + 2*S1 + 4*S2 + 8*S3 ; set iff >= 5
    return S3 | (S2 & (S1 | S0));
}

__device__ __forceinline__ uint64_t mk_policy_evict_last() {
    uint64_t p;
    asm("createpolicy.fractional.L2::evict_last.b64 %0, 1.0;" : "=l"(p));
    return p;
}

__device__ __forceinline__ uint64_t mk_policy_evict_first() {
    uint64_t p;
    asm("createpolicy.fractional.L2::evict_first.b64 %0, 1.0;" : "=l"(p));
    return p;
}

__device__ __forceinline__ uint4 ldg_nc_evl(const uint4* p, uint64_t pol) {
    uint4 v;
    asm volatile("ld.global.nc.L2::cache_hint.v4.u32 {%0,%1,%2,%3}, [%4], %5;"
                 : "=r"(v.x), "=r"(v.y), "=r"(v.z), "=r"(v.w)
                 : "l"(p), "l"(pol));
    return v;
}

__device__ __forceinline__ void st_evf(float4* p, float4 v, uint64_t pol) {
    asm volatile("st.global.L2::cache_hint.v4.f32 [%0], {%1,%2,%3,%4}, %5;"
                 :: "l"(p), "f"(v.x), "f"(v.y), "f"(v.z), "f"(v.w), "l"(pol)
                 : "memory");
}

__global__ void __launch_bounds__(128)
majority_vote_kernel(const uint4* __restrict__ src, float4* __restrict__ out, int m4) {
    int idx = blockIdx.x * blockDim.x + threadIdx.x;
    if (idx >= m4) return;

    const uint64_t pol_in  = mk_policy_evict_last();
    const uint64_t pol_out = mk_policy_evict_first();

    // 8 front-batched independent 128-bit nc loads, evict_last (MLP = 8).
    uint4 v0 = ldg_nc_evl(src + 0 * (size_t)m4 + idx, pol_in);
    uint4 v1 = ldg_nc_evl(src + 1 * (size_t)m4 + idx, pol_in);
    uint4 v2 = ldg_nc_evl(src + 2 * (size_t)m4 + idx, pol_in);
    uint4 v3 = ldg_nc_evl(src + 3 * (size_t)m4 + idx, pol_in);
    uint4 v4 = ldg_nc_evl(src + 4 * (size_t)m4 + idx, pol_in);
    uint4 v5 = ldg_nc_evl(src + 5 * (size_t)m4 + idx, pol_in);
    uint4 v6 = ldg_nc_evl(src + 6 * (size_t)m4 + idx, pol_in);
    uint4 v7 = ldg_nc_evl(src + 7 * (size_t)m4 + idx, pol_in);

    float4 r;
    r.x = __int2float_rn((int)maj8(v0.x, v1.x, v2.x, v3.x, v4.x, v5.x, v6.x, v7.x));
    r.y = __int2float_rn((int)maj8(v0.y, v1.y, v2.y, v3.y, v4.y, v5.y, v6.y, v7.y));
    r.z = __int2float_rn((int)maj8(v0.z, v1.z, v2.z, v3.z, v4.z, v5.z, v6.z, v7.z));
    r.w = __int2float_rn((int)maj8(v0.w, v1.w, v2.w, v3.w, v4.w, v5.w, v6.w, v7.w));
    st_evf(out + idx, r, pol_out);
}

extern "C" void kernel_launch(void* const* d_in, const int* in_sizes, int n_in,
                              void* d_out, int out_size) {
    const uint32_t* src = (const uint32_t*)d_in[1];
    long long n_src = in_sizes[1];
    if (n_in > 1 && in_sizes[0] > in_sizes[1]) { src = (const uint32_t*)d_in[0]; n_src = in_sizes[0]; }

    int M  = (int)(n_src / 8);     // packed words per voter == out_size
    int m4 = M / 4;                // uint4 chunks (262144)

    int threads = 128;
    int blocks  = (m4 + threads - 1) / threads;   // 2048
    majority_vote_kernel<<<blocks, threads>>>((const uint4*)src, (float4*)d_out, m4);
}